// round 8
// baseline (speedup 1.0000x reference)
#include <cuda_runtime.h>
#include <cuda_bf16.h>
#include <cstdint>

typedef unsigned long long ull;

// ---------------------------------------------------------------------------
// LSTM autoencoder: 4 layers, B=64, T=1024, H in {256,128,256,256}.
//   zx GEMMs: mma.sync bf16 split-precision (hi/lo, 3 products, fp32 accum)
//   recurrence: persistent kernel, 8 batch groups x 16 col CTAs.
//     Preferred: 16-CTA clusters, h exchange via DSMEM + mbarrier.
//       (R7 crash fixed: no remote ops on last step, cluster fence before
//        release-arrive, trailing cluster sync before exit.)
//     Fallback:  L2 flag sync (round-6 proven path).
// ---------------------------------------------------------------------------

#define T_STEPS 1024
#define BATCH   64

__device__ float g_zx[67108864];           // [B*T][4*256] max
__device__ float g_bufA[16777216];         // [B][T][256]
__device__ float g_bufB[8388608];          // [B][T][128]
__device__ int   g_flags[4 * 8 * T_STEPS]; // [layer][G][T] (fallback path)
__device__ __nv_bfloat16 g_ahi[16777216];  // A hi  [M][K]
__device__ __nv_bfloat16 g_alo[16777216];  // A lo
__device__ __nv_bfloat16 g_wthi[262144];   // W^T hi [N][K]
__device__ __nv_bfloat16 g_wtlo[262144];   // W^T lo

// -------------------- scalar primitives ------------------------------------
__device__ __forceinline__ int ld_acquire_gpu(const int* p) {
    int v;
    asm volatile("ld.acquire.gpu.global.s32 %0, [%1];" : "=r"(v) : "l"(p) : "memory");
    return v;
}
__device__ __forceinline__ void red_release_gpu_add(int* p, int v) {
    asm volatile("red.release.gpu.global.add.s32 [%0], %1;" :: "l"(p), "r"(v) : "memory");
}
__device__ __forceinline__ ull pack2(float x, float y) {
    ull r; asm("mov.b64 %0, {%1, %2};" : "=l"(r) : "f"(x), "f"(y)); return r;
}
__device__ __forceinline__ ull ffma2(ull a, ull b, ull c) {
    ull d; asm("fma.rn.f32x2 %0, %1, %2, %3;" : "=l"(d) : "l"(a), "l"(b), "l"(c)); return d;
}
__device__ __forceinline__ float sum2(ull a) {
    float x, y; asm("mov.b64 {%0, %1}, %2;" : "=f"(x), "=f"(y) : "l"(a)); return x + y;
}
__device__ __forceinline__ uint32_t smem_u32(const void* p) {
    uint32_t a;
    asm("{ .reg .u64 t; cvta.to.shared.u64 t, %1; cvt.u32.u64 %0, t; }" : "=r"(a) : "l"(p));
    return a;
}

// -------------------- cluster / DSMEM primitives ----------------------------
__device__ __forceinline__ uint32_t mapa_u32(uint32_t localaddr, uint32_t rank) {
    uint32_t r;
    asm("mapa.shared::cluster.u32 %0, %1, %2;" : "=r"(r) : "r"(localaddr), "r"(rank));
    return r;
}
__device__ __forceinline__ void st_cluster_f32(uint32_t addr, float v) {
    asm volatile("st.shared::cluster.f32 [%0], %1;" :: "r"(addr), "f"(v) : "memory");
}
__device__ __forceinline__ void fence_cluster() {
    asm volatile("fence.acq_rel.cluster;" ::: "memory");
}
__device__ __forceinline__ void mbar_arrive_cluster(uint32_t mb_local, uint32_t rank) {
    asm volatile(
        "{ .reg .b32 ra; mapa.shared::cluster.u32 ra, %0, %1;\n\t"
        "mbarrier.arrive.release.cluster.shared::cluster.b64 _, [ra]; }"
        :: "r"(mb_local), "r"(rank) : "memory");
}
__device__ __forceinline__ void mbar_wait_cluster(uint32_t mb, uint32_t parity) {
    uint32_t done;
    asm volatile(
        "{ .reg .pred p; mbarrier.try_wait.parity.acquire.cluster.shared::cta.b64 p, [%1], %2;\n\t"
        "selp.b32 %0, 1, 0, p; }"
        : "=r"(done) : "r"(mb), "r"(parity) : "memory");
    if (!done) {
        asm volatile(
            "{ .reg .pred P1;\n\t"
            "WL_%=: mbarrier.try_wait.parity.acquire.cluster.shared::cta.b64 P1, [%0], %1, 0x989680;\n\t"
            "@P1 bra.uni WD_%=;\n\t"
            "bra.uni WL_%=;\n\t"
            "WD_%=: }"
            :: "r"(mb), "r"(parity) : "memory");
    }
}
#define MBAR_INIT(mb, cnt) \
    asm volatile("mbarrier.init.shared.b64 [%0], %1;" :: "r"(mb), "r"((uint32_t)(cnt)) : "memory")
#define CLUSTER_SYNC_() do { \
    asm volatile("barrier.cluster.arrive.aligned;" ::: "memory"); \
    asm volatile("barrier.cluster.wait.aligned;" ::: "memory"); \
} while (0)

// -------------------- tensor-core primitives --------------------------------
__device__ __forceinline__ void ldmat4(uint32_t* r, uint32_t addr) {
    asm volatile("ldmatrix.sync.aligned.m8n8.x4.shared.b16 {%0,%1,%2,%3}, [%4];"
        : "=r"(r[0]), "=r"(r[1]), "=r"(r[2]), "=r"(r[3]) : "r"(addr));
}
__device__ __forceinline__ void mma16816(float* c, const uint32_t* a, const uint32_t* b) {
    asm volatile(
        "mma.sync.aligned.m16n8k16.row.col.f32.bf16.bf16.f32 "
        "{%0,%1,%2,%3}, {%4,%5,%6,%7}, {%8,%9}, {%0,%1,%2,%3};"
        : "+f"(c[0]), "+f"(c[1]), "+f"(c[2]), "+f"(c[3])
        : "r"(a[0]), "r"(a[1]), "r"(a[2]), "r"(a[3]), "r"(b[0]), "r"(b[1]));
}

// ---------------------------------------------------------------------------
// split_bf16: x -> (hi, lo) bf16
// ---------------------------------------------------------------------------
__global__ __launch_bounds__(256) void split_bf16(
    const float* __restrict__ x, __nv_bfloat16* __restrict__ hi,
    __nv_bfloat16* __restrict__ lo, int n4)
{
    int i = blockIdx.x * 256 + threadIdx.x;
    if (i >= n4) return;
    float4 v = ((const float4*)x)[i];
    __nv_bfloat16 h0 = __float2bfloat16(v.x), h1 = __float2bfloat16(v.y);
    __nv_bfloat16 h2 = __float2bfloat16(v.z), h3 = __float2bfloat16(v.w);
    __nv_bfloat16 l0 = __float2bfloat16(v.x - __bfloat162float(h0));
    __nv_bfloat16 l1 = __float2bfloat16(v.y - __bfloat162float(h1));
    __nv_bfloat16 l2 = __float2bfloat16(v.z - __bfloat162float(h2));
    __nv_bfloat16 l3 = __float2bfloat16(v.w - __bfloat162float(h3));
    ((__nv_bfloat162*)hi)[2 * i + 0] = __nv_bfloat162(h0, h1);
    ((__nv_bfloat162*)hi)[2 * i + 1] = __nv_bfloat162(h2, h3);
    ((__nv_bfloat162*)lo)[2 * i + 0] = __nv_bfloat162(l0, l1);
    ((__nv_bfloat162*)lo)[2 * i + 1] = __nv_bfloat162(l2, l3);
}

// ---------------------------------------------------------------------------
// wsplit_t: W[K][N] fp32 -> Wt hi/lo [N][K] bf16
// ---------------------------------------------------------------------------
__global__ void wsplit_t(const float* __restrict__ W,
                         __nv_bfloat16* __restrict__ Th,
                         __nv_bfloat16* __restrict__ Tl, int K, int N)
{
    __shared__ float tile[32][33];
    int n0 = blockIdx.x * 32, k0 = blockIdx.y * 32;
    int tx = threadIdx.x, ty = threadIdx.y;
#pragma unroll
    for (int j = 0; j < 32; j += 8)
        tile[ty + j][tx] = W[(size_t)(k0 + ty + j) * N + n0 + tx];
    __syncthreads();
#pragma unroll
    for (int j = 0; j < 32; j += 8) {
        float v = tile[tx][ty + j];
        __nv_bfloat16 h = __float2bfloat16(v);
        __nv_bfloat16 l = __float2bfloat16(v - __bfloat162float(h));
        Th[(size_t)(n0 + ty + j) * K + k0 + tx] = h;
        Tl[(size_t)(n0 + ty + j) * K + k0 + tx] = l;
    }
}

// ---------------------------------------------------------------------------
// gemm_mma_split (round-6 proven)
// ---------------------------------------------------------------------------
__global__ __launch_bounds__(256, 2) void gemm_mma_split(
    const __nv_bfloat16* __restrict__ Ahi, const __nv_bfloat16* __restrict__ Alo,
    const __nv_bfloat16* __restrict__ Bhi, const __nv_bfloat16* __restrict__ Blo,
    const float* __restrict__ bias, float* __restrict__ C,
    int M, int N, int K)
{
    __shared__ __nv_bfloat16 sAh[128][40], sAl[128][40], sBh[128][40], sBl[128][40];

    int tid = threadIdx.x;
    int wid = tid >> 5, lid = tid & 31;
    int wm = wid >> 2, wn = wid & 3;
    int g  = lid >> 2, tg = lid & 3;
    int lj = lid >> 3, lr = lid & 7;
    int bn = blockIdx.x * 128;
    int bm = blockIdx.y * 128;

    float acc[4][4][4];
#pragma unroll
    for (int mt = 0; mt < 4; mt++)
#pragma unroll
        for (int nt = 0; nt < 4; nt++)
#pragma unroll
            for (int q = 0; q < 4; q++) acc[mt][nt][q] = 0.f;

    uint32_t baseAh = smem_u32(&sAh[0][0]), baseAl = smem_u32(&sAl[0][0]);
    uint32_t baseBh = smem_u32(&sBh[0][0]), baseBl = smem_u32(&sBl[0][0]);

    int aRowL = wm * 64 + (lj & 1) * 8 + lr;
    int aColL = (lj >> 1) * 8;
    int bRowL = wn * 32 + (lj >> 1) * 8 + lr;
    int bColL = (lj & 1) * 8;

    for (int kc = 0; kc < K; kc += 32) {
        __syncthreads();
        for (int i = tid; i < 512; i += 256) {
            int r = i >> 2, u = (i & 3) * 8;
            size_t ga = (size_t)(bm + r) * K + kc + u;
            size_t gb = (size_t)(bn + r) * K + kc + u;
            *(uint4*)&sAh[r][u] = *(const uint4*)&Ahi[ga];
            *(uint4*)&sAl[r][u] = *(const uint4*)&Alo[ga];
            *(uint4*)&sBh[r][u] = *(const uint4*)&Bhi[gb];
            *(uint4*)&sBl[r][u] = *(const uint4*)&Blo[gb];
        }
        __syncthreads();

#pragma unroll
        for (int ks2 = 0; ks2 < 32; ks2 += 16) {
            uint32_t bh[2][4], bl[2][4];
#pragma unroll
            for (int ntp = 0; ntp < 2; ntp++) {
                uint32_t off = (uint32_t)((bRowL + ntp * 16) * 40 + ks2 + bColL) * 2;
                ldmat4(bh[ntp], baseBh + off);
                ldmat4(bl[ntp], baseBl + off);
            }
#pragma unroll
            for (int mt = 0; mt < 4; mt++) {
                uint32_t ah[4], al[4];
                uint32_t off = (uint32_t)((aRowL + mt * 16) * 40 + ks2 + aColL) * 2;
                ldmat4(ah, baseAh + off);
                ldmat4(al, baseAl + off);
#pragma unroll
                for (int nt = 0; nt < 4; nt++) {
                    const uint32_t* pbh = &bh[nt >> 1][(nt & 1) * 2];
                    const uint32_t* pbl = &bl[nt >> 1][(nt & 1) * 2];
                    mma16816(acc[mt][nt], ah, pbh);
                    mma16816(acc[mt][nt], ah, pbl);
                    mma16816(acc[mt][nt], al, pbh);
                }
            }
        }
    }

#pragma unroll
    for (int mt = 0; mt < 4; mt++) {
#pragma unroll
        for (int nt = 0; nt < 4; nt++) {
            int row = bm + wm * 64 + mt * 16 + g;
            int col = bn + wn * 32 + nt * 8 + tg * 2;
            float b0 = __ldg(&bias[col]), b1 = __ldg(&bias[col + 1]);
            float2 v0 = make_float2(acc[mt][nt][0] + b0, acc[mt][nt][1] + b1);
            float2 v1 = make_float2(acc[mt][nt][2] + b0, acc[mt][nt][3] + b1);
            *(float2*)&C[(size_t)row * N + col]       = v0;
            *(float2*)&C[(size_t)(row + 8) * N + col] = v1;
        }
    }
}

// ---------------------------------------------------------------------------
// lstm_rec_dsmem: cluster of 16 CTAs = one batch group (Bg=8 rows).
// Per step each CTA writes its h slice into all 16 CTAs' smem
// (st.shared::cluster), fences at cluster scope, then 16 release-arrives.
// Last step publishes nothing remotely; trailing cluster sync before exit.
// ---------------------------------------------------------------------------
template <int H, int SL, int KP, int CB, int RS>
__global__ __launch_bounds__(256, 1) void lstm_rec_dsmem(
    const float* __restrict__ zx, const float* __restrict__ U,
    float* __restrict__ out)
{
    constexpr int N4   = 4 * H;
    constexpr int Bg   = 8;
    constexpr int Pc   = 16;
    constexpr int NH   = H / Pc;
    constexpr int NCZ  = 4 * NH;
    constexpr int K2   = H / 2;
    constexpr int CW   = 4;
    constexpr int RT   = Bg / RS;
    constexpr int NRED = Bg * NH;
    constexpr int HB   = Bg * H;          // floats per h buffer
    static_assert(SL * KP == K2 && CB * CW == NCZ && SL * CB * RS == 256, "split");

    extern __shared__ float dynsm[];
    float* hb = dynsm;                    // [2][Bg][H]
    float* zp = dynsm + 2 * HB;           // [SL][Bg][NCZ]
    __shared__ __align__(8) ull mbar[2];

    int tid = threadIdx.x;
    int g   = blockIdx.x >> 4;
    int cb  = blockIdx.x & 15;            // == cluster rank
    int jb  = cb * NH;

    uint32_t hb_u   = smem_u32(hb);
    uint32_t mbar_u = smem_u32(&mbar[0]);

    if (tid == 0) { MBAR_INIT(mbar_u, 16); MBAR_INIT(mbar_u + 8, 16); }
    CLUSTER_SYNC_();

    // thread decomposition (matmul)
    int s   = tid / (CB * RS);
    int rem = tid % (CB * RS);
    int cb2 = rem / RS;
    int rs  = rem % RS;

    // U slice -> registers (one-time)
    ull Ureg[KP][CW];
#pragma unroll
    for (int kk = 0; kk < KP; kk++)
#pragma unroll
        for (int cw = 0; cw < CW; cw++) {
            int c    = cb2 * CW + cw;
            int gi   = c / NH;
            int j    = c % NH;
            int gcol = gi * H + jb + j;
            int k2   = s * KP + kk;
            Ureg[kk][cw] = pack2(__ldg(&U[(size_t)(2 * k2) * N4 + gcol]),
                                 __ldg(&U[(size_t)(2 * k2 + 1) * N4 + gcol]));
        }

    // reduce identity (tid < NRED)
    int rr = tid / NH;
    int jj = tid % NH;
    int bglob = g * Bg + rr;
    float creg = 0.f;

    // Precompute remote DSMEM addresses of this thread's h slot (buffer 0).
    uint32_t slot = hb_u + (uint32_t)(rr * H + jb + jj) * 4u;
    uint32_t radr[16];
#pragma unroll
    for (int c = 0; c < 16; c++) radr[c] = mapa_u32(slot, (uint32_t)c);

    for (int t = 0; t < T_STEPS; t++) {
        // Prefetch zx (overlaps the wait).
        float zx0 = 0.f, zx1 = 0.f, zx2 = 0.f, zx3 = 0.f;
        if (tid < NRED) {
            size_t basei = ((size_t)bglob * T_STEPS + t) * N4 + jb + jj;
            zx0 = zx[basei + 0 * (size_t)H];
            zx1 = zx[basei + 1 * (size_t)H];
            zx2 = zx[basei + 2 * (size_t)H];
            zx3 = zx[basei + 3 * (size_t)H];
        }

        float z0 = 0.f, z1 = 0.f, z2 = 0.f, z3 = 0.f;
        if (t > 0) {
            int pb = (t - 1) & 1;
            mbar_wait_cluster(mbar_u + 8 * pb, ((t - 1) >> 1) & 1);

            const ull* h2 = (const ull*)(hb + pb * HB);  // [Bg][K2]

            ull acc[RT][CW];
#pragma unroll
            for (int i = 0; i < RT; i++)
#pragma unroll
                for (int cw = 0; cw < CW; cw++) acc[i][cw] = 0ull;

#pragma unroll
            for (int kk = 0; kk < KP; kk++) {
                int k2 = s * KP + kk;
                ull hv[RT];
#pragma unroll
                for (int i = 0; i < RT; i++)
                    hv[i] = h2[(rs * RT + i) * K2 + k2];
#pragma unroll
                for (int i = 0; i < RT; i++)
#pragma unroll
                    for (int cw = 0; cw < CW; cw++)
                        acc[i][cw] = ffma2(hv[i], Ureg[kk][cw], acc[i][cw]);
            }
#pragma unroll
            for (int i = 0; i < RT; i++) {
                float4 v;
                v.x = sum2(acc[i][0]);
                v.y = sum2(acc[i][1]);
                v.z = sum2(acc[i][2]);
                v.w = sum2(acc[i][3]);
                *(float4*)&zp[(s * Bg + rs * RT + i) * NCZ + cb2 * CW] = v;
            }
            __syncthreads();

            if (tid < NRED) {
#pragma unroll
                for (int s2 = 0; s2 < SL; s2++) {
                    const float* zr = &zp[(s2 * Bg + rr) * NCZ];
                    z0 += zr[0 * NH + jj];
                    z1 += zr[1 * NH + jj];
                    z2 += zr[2 * NH + jj];
                    z3 += zr[3 * NH + jj];
                }
            }
        }

        // Gates + state update; publish h_t (global always; remote smem only
        // if a consumer step exists).
        bool publish = (t < T_STEPS - 1);
        if (tid < NRED) {
            float zi = zx0 + z0, zf = zx1 + z1, zg = zx2 + z2, zo = zx3 + z3;
            float si = 1.f / (1.f + __expf(-zi));
            float sf = 1.f / (1.f + __expf(-zf));
            float so = 1.f / (1.f + __expf(-zo));
            float gg = zg > 0.f ? zg : 0.f;
            creg = sf * creg + si * gg;
            float cr = creg > 0.f ? creg : 0.f;
            float hval = so * cr;
            out[((size_t)bglob * T_STEPS + t) * H + jb + jj] = hval;
            if (publish) {
                uint32_t boff = (uint32_t)((t & 1) * HB * 4);
#pragma unroll
                for (int c = 0; c < 16; c++)
                    st_cluster_f32(radr[c] + boff, hval);
                fence_cluster();   // make remote stores cluster-visible
            }
        }
        if (publish) {
            __syncthreads();       // all stores + fences done before arrives
            if (tid < 16)
                mbar_arrive_cluster(mbar_u + 8 * (t & 1), (uint32_t)tid);
        }
    }

    // No CTA may exit while peers might still address our smem.
    CLUSTER_SYNC_();
}

// ---------------------------------------------------------------------------
// lstm_rec_flag: round-6 proven fallback (L2 flag sync).
// ---------------------------------------------------------------------------
template <int H, int SL, int KP, int CB, int RS>
__global__ __launch_bounds__(256, 1) void lstm_rec_flag(
    const float* __restrict__ zx, const float* __restrict__ U,
    float* __restrict__ out, int* __restrict__ flags)
{
    constexpr int N4   = 4 * H;
    constexpr int Bg   = 8;
    constexpr int Pc   = 16;
    constexpr int NH   = H / Pc;
    constexpr int NCZ  = 4 * NH;
    constexpr int K2   = H / 2;
    constexpr int CW   = 4;
    constexpr int RT   = Bg / RS;
    constexpr int NRED = Bg * NH;
    static_assert(SL * KP == K2 && CB * CW == NCZ && SL * CB * RS == 256, "split");

    __shared__ ull   h2[Bg * K2];
    __shared__ float zp[SL * Bg * NCZ];
    float* h_s = (float*)h2;

    int tid = threadIdx.x;
    int g   = blockIdx.x >> 4;
    int cb  = blockIdx.x & 15;
    int jb  = cb * NH;

    int s   = tid / (CB * RS);
    int rem = tid % (CB * RS);
    int cb2 = rem / RS;
    int rs  = rem % RS;

    ull Ureg[KP][CW];
#pragma unroll
    for (int kk = 0; kk < KP; kk++)
#pragma unroll
        for (int cw = 0; cw < CW; cw++) {
            int c    = cb2 * CW + cw;
            int gi   = c / NH;
            int j    = c % NH;
            int gcol = gi * H + jb + j;
            int k2   = s * KP + kk;
            Ureg[kk][cw] = pack2(__ldg(&U[(size_t)(2 * k2) * N4 + gcol]),
                                 __ldg(&U[(size_t)(2 * k2 + 1) * N4 + gcol]));
        }

    int rr = tid / NH;
    int jj = tid % NH;
    int bglob = g * Bg + rr;
    float creg = 0.f;

    int* flagrd = flags + g * T_STEPS;
    __syncthreads();

    for (int t = 0; t < T_STEPS; t++) {
        float zx0 = 0.f, zx1 = 0.f, zx2 = 0.f, zx3 = 0.f;
        if (tid < NRED) {
            size_t basei = ((size_t)bglob * T_STEPS + t) * N4 + jb + jj;
            zx0 = zx[basei + 0 * (size_t)H];
            zx1 = zx[basei + 1 * (size_t)H];
            zx2 = zx[basei + 2 * (size_t)H];
            zx3 = zx[basei + 3 * (size_t)H];
        }

        float z0 = 0.f, z1 = 0.f, z2 = 0.f, z3 = 0.f;
        if (t > 0) {
            if (tid == 0) {
                while (ld_acquire_gpu(&flagrd[t - 1]) < Pc) { }
            }
            __syncthreads();

            for (int i4 = tid; i4 < (Bg * H) / 4; i4 += 256) {
                int idx = i4 * 4;
                int r = idx / H, k = idx % H;
                *(float4*)&h_s[idx] =
                    *(const float4*)&out[((size_t)(g * Bg + r) * T_STEPS + (t - 1)) * H + k];
            }
            __syncthreads();

            ull acc[RT][CW];
#pragma unroll
            for (int i = 0; i < RT; i++)
#pragma unroll
                for (int cw = 0; cw < CW; cw++) acc[i][cw] = 0ull;

#pragma unroll
            for (int kk = 0; kk < KP; kk++) {
                int k2 = s * KP + kk;
                ull hv[RT];
#pragma unroll
                for (int i = 0; i < RT; i++)
                    hv[i] = h2[(rs * RT + i) * K2 + k2];
#pragma unroll
                for (int i = 0; i < RT; i++)
#pragma unroll
                    for (int cw = 0; cw < CW; cw++)
                        acc[i][cw] = ffma2(hv[i], Ureg[kk][cw], acc[i][cw]);
            }
#pragma unroll
            for (int i = 0; i < RT; i++) {
                float4 v;
                v.x = sum2(acc[i][0]);
                v.y = sum2(acc[i][1]);
                v.z = sum2(acc[i][2]);
                v.w = sum2(acc[i][3]);
                *(float4*)&zp[(s * Bg + rs * RT + i) * NCZ + cb2 * CW] = v;
            }
            __syncthreads();

            if (tid < NRED) {
#pragma unroll
                for (int s2 = 0; s2 < SL; s2++) {
                    const float* zr = &zp[(s2 * Bg + rr) * NCZ];
                    z0 += zr[0 * NH + jj];
                    z1 += zr[1 * NH + jj];
                    z2 += zr[2 * NH + jj];
                    z3 += zr[3 * NH + jj];
                }
            }
        }

        if (tid < NRED) {
            float zi = zx0 + z0, zf = zx1 + z1, zg = zx2 + z2, zo = zx3 + z3;
            float si = 1.f / (1.f + __expf(-zi));
            float sf = 1.f / (1.f + __expf(-zf));
            float so = 1.f / (1.f + __expf(-zo));
            float gg = zg > 0.f ? zg : 0.f;
            creg = sf * creg + si * gg;
            float cr = creg > 0.f ? creg : 0.f;
            out[((size_t)bglob * T_STEPS + t) * H + jb + jj] = so * cr;
        }
        __syncthreads();
        if (tid == 0) red_release_gpu_add(&flags[g * T_STEPS + t], 1);
    }
}

// ---------------------------------------------------------------------------
extern "C" void kernel_launch(void* const* d_in, const int* in_sizes, int n_in,
                              void* d_out, int out_size)
{
    const float* x  = (const float*)d_in[0];
    const float* W1 = (const float*)d_in[1];
    const float* U1 = (const float*)d_in[2];
    const float* b1 = (const float*)d_in[3];
    const float* W2 = (const float*)d_in[4];
    const float* U2 = (const float*)d_in[5];
    const float* b2 = (const float*)d_in[6];
    const float* W3 = (const float*)d_in[7];
    const float* U3 = (const float*)d_in[8];
    const float* b3 = (const float*)d_in[9];
    const float* W4 = (const float*)d_in[10];
    const float* U4 = (const float*)d_in[11];
    const float* b4 = (const float*)d_in[12];
    float* out = (float*)d_out;

    void *p;
    cudaGetSymbolAddress(&p, g_zx);    float* zx    = (float*)p;
    cudaGetSymbolAddress(&p, g_bufA);  float* bufA  = (float*)p;
    cudaGetSymbolAddress(&p, g_bufB);  float* bufB  = (float*)p;
    cudaGetSymbolAddress(&p, g_flags); int*   flags = (int*)p;
    cudaGetSymbolAddress(&p, g_ahi);   __nv_bfloat16* ahi  = (__nv_bfloat16*)p;
    cudaGetSymbolAddress(&p, g_alo);   __nv_bfloat16* alo  = (__nv_bfloat16*)p;
    cudaGetSymbolAddress(&p, g_wthi);  __nv_bfloat16* wthi = (__nv_bfloat16*)p;
    cudaGetSymbolAddress(&p, g_wtlo);  __nv_bfloat16* wtlo = (__nv_bfloat16*)p;

    const int M = BATCH * T_STEPS;  // 65536

    const int DSM256 = 2 * 8 * 256 * 4 + 16 * 8 * 64 * 4;   // 49152
    const int DSM128 = 2 * 8 * 128 * 4 + 8 * 8 * 32 * 4;    // 16384

    auto* k256 = lstm_rec_dsmem<256, 16, 8, 16, 1>;
    auto* k128 = lstm_rec_dsmem<128, 8, 8, 8, 4>;
    cudaFuncSetAttribute(k256, cudaFuncAttributeMaxDynamicSharedMemorySize, DSM256);
    cudaFuncSetAttribute(k256, cudaFuncAttributeNonPortableClusterSizeAllowed, 1);
    cudaFuncSetAttribute(k128, cudaFuncAttributeMaxDynamicSharedMemorySize, DSM128);
    cudaFuncSetAttribute(k128, cudaFuncAttributeNonPortableClusterSizeAllowed, 1);

    cudaLaunchAttribute cattr[1];
    cattr[0].id = cudaLaunchAttributeClusterDimension;
    cattr[0].val.clusterDim = {16, 1, 1};

    cudaLaunchConfig_t cfg256 = {};
    cfg256.gridDim = {128, 1, 1};
    cfg256.blockDim = {256, 1, 1};
    cfg256.dynamicSmemBytes = DSM256;
    cfg256.attrs = cattr;
    cfg256.numAttrs = 1;

    cudaLaunchConfig_t cfg128 = cfg256;
    cfg128.dynamicSmemBytes = DSM128;

    int nclu = 0;
    cudaError_t e = cudaOccupancyMaxActiveClusters(&nclu, k256, &cfg256);
    bool use_dsmem = (e == cudaSuccess && nclu >= 1);
    if (use_dsmem) {
        int nclu2 = 0;
        e = cudaOccupancyMaxActiveClusters(&nclu2, k128, &cfg128);
        use_dsmem = (e == cudaSuccess && nclu2 >= 1);
    }
    cudaGetLastError();

    cudaMemsetAsync(flags, 0, 4 * 8 * T_STEPS * sizeof(int));

    // ---- Layer 1: F=256 -> H=256 ----
    split_bf16<<<M * 256 / 4 / 256, 256>>>(x, ahi, alo, M * 256 / 4);
    wsplit_t<<<dim3(1024 / 32, 256 / 32), dim3(32, 8)>>>(W1, wthi, wtlo, 256, 1024);
    gemm_mma_split<<<dim3(8, M / 128), 256>>>(ahi, alo, wthi, wtlo, b1, zx, M, 1024, 256);
    if (use_dsmem) cudaLaunchKernelEx(&cfg256, k256, (const float*)zx, U1, bufA);
    else lstm_rec_flag<256, 16, 8, 16, 1><<<128, 256>>>(zx, U1, bufA, flags + 0 * 8 * T_STEPS);

    // ---- Layer 2: F=256 -> H=128 ----
    split_bf16<<<M * 256 / 4 / 256, 256>>>(bufA, ahi, alo, M * 256 / 4);
    wsplit_t<<<dim3(512 / 32, 256 / 32), dim3(32, 8)>>>(W2, wthi, wtlo, 256, 512);
    gemm_mma_split<<<dim3(4, M / 128), 256>>>(ahi, alo, wthi, wtlo, b2, zx, M, 512, 256);
    if (use_dsmem) cudaLaunchKernelEx(&cfg128, k128, (const float*)zx, U2, bufB);
    else lstm_rec_flag<128, 8, 8, 8, 4><<<128, 256>>>(zx, U2, bufB, flags + 1 * 8 * T_STEPS);

    // ---- Layer 3: F=128 -> H=256 ----
    split_bf16<<<M * 128 / 4 / 256, 256>>>(bufB, ahi, alo, M * 128 / 4);
    wsplit_t<<<dim3(1024 / 32, 128 / 32), dim3(32, 8)>>>(W3, wthi, wtlo, 128, 1024);
    gemm_mma_split<<<dim3(8, M / 128), 256>>>(ahi, alo, wthi, wtlo, b3, zx, M, 1024, 128);
    if (use_dsmem) cudaLaunchKernelEx(&cfg256, k256, (const float*)zx, U3, bufA);
    else lstm_rec_flag<256, 16, 8, 16, 1><<<128, 256>>>(zx, U3, bufA, flags + 2 * 8 * T_STEPS);

    // ---- Layer 4: F=256 -> H=256 ----
    split_bf16<<<M * 256 / 4 / 256, 256>>>(bufA, ahi, alo, M * 256 / 4);
    wsplit_t<<<dim3(1024 / 32, 256 / 32), dim3(32, 8)>>>(W4, wthi, wtlo, 256, 1024);
    gemm_mma_split<<<dim3(8, M / 128), 256>>>(ahi, alo, wthi, wtlo, b4, zx, M, 1024, 256);
    if (use_dsmem) cudaLaunchKernelEx(&cfg256, k256, (const float*)zx, U4, out);
    else lstm_rec_flag<256, 16, 8, 16, 1><<<128, 256>>>(zx, U4, out, flags + 3 * 8 * T_STEPS);
}

// round 13
// speedup vs baseline: 1.0409x; 1.0409x over previous
#include <cuda_runtime.h>
#include <cuda_bf16.h>
#include <cstdint>

typedef unsigned long long ull;

// ---------------------------------------------------------------------------
// LSTM autoencoder: 4 layers, B=64, T=1024, H in {256,128,256,256}.
//   zx GEMMs: mma.sync bf16 split-precision (hi/lo, 3 products, fp32 accum)
//   recurrence: persistent kernel, 8 batch groups x 16 col CTAs.
//     Preferred: 16-CTA clusters; h exchange via PLAIN st.shared::cluster.v4
//       pushed by 16 designated sender threads, each followed by its own
//       mbarrier.arrive.release (release orders that thread's stores; no
//       fences, no st.async, 16 arrivals per mbar per phase).
//     Fallback:  L2 flag sync (round-6 proven path, 12.2 ms total).
// ---------------------------------------------------------------------------

#define T_STEPS 1024
#define BATCH   64

__device__ float g_zx[67108864];           // [B*T][4*256] max
__device__ float g_bufA[16777216];         // [B][T][256]
__device__ float g_bufB[8388608];          // [B][T][128]
__device__ int   g_flags[4 * 8 * T_STEPS]; // [layer][G][T] (fallback path)
__device__ __nv_bfloat16 g_ahi[16777216];  // A hi  [M][K]
__device__ __nv_bfloat16 g_alo[16777216];  // A lo
__device__ __nv_bfloat16 g_wthi[262144];   // W^T hi [N][K]
__device__ __nv_bfloat16 g_wtlo[262144];   // W^T lo

// -------------------- scalar primitives ------------------------------------
__device__ __forceinline__ int ld_acquire_gpu(const int* p) {
    int v;
    asm volatile("ld.acquire.gpu.global.s32 %0, [%1];" : "=r"(v) : "l"(p) : "memory");
    return v;
}
__device__ __forceinline__ void red_release_gpu_add(int* p, int v) {
    asm volatile("red.release.gpu.global.add.s32 [%0], %1;" :: "l"(p), "r"(v) : "memory");
}
__device__ __forceinline__ ull pack2(float x, float y) {
    ull r; asm("mov.b64 %0, {%1, %2};" : "=l"(r) : "f"(x), "f"(y)); return r;
}
__device__ __forceinline__ ull ffma2(ull a, ull b, ull c) {
    ull d; asm("fma.rn.f32x2 %0, %1, %2, %3;" : "=l"(d) : "l"(a), "l"(b), "l"(c)); return d;
}
__device__ __forceinline__ float sum2(ull a) {
    float x, y; asm("mov.b64 {%0, %1}, %2;" : "=f"(x), "=f"(y) : "l"(a)); return x + y;
}
__device__ __forceinline__ uint32_t smem_u32(const void* p) {
    uint32_t a;
    asm("{ .reg .u64 t; cvta.to.shared.u64 t, %1; cvt.u32.u64 %0, t; }" : "=r"(a) : "l"(p));
    return a;
}

// -------------------- cluster / DSMEM primitives ----------------------------
__device__ __forceinline__ uint32_t mapa_u32(uint32_t localaddr, uint32_t rank) {
    uint32_t r;
    asm("mapa.shared::cluster.u32 %0, %1, %2;" : "=r"(r) : "r"(localaddr), "r"(rank));
    return r;
}
__device__ __forceinline__ void st_cluster_v4(uint32_t addr, float4 v) {
    asm volatile("st.shared::cluster.v4.f32 [%0], {%1,%2,%3,%4};"
        :: "r"(addr), "f"(v.x), "f"(v.y), "f"(v.z), "f"(v.w) : "memory");
}
__device__ __forceinline__ void mbar_arrive_remote(uint32_t remote_mb) {
    asm volatile("mbarrier.arrive.release.cluster.shared::cluster.b64 _, [%0];"
                 :: "r"(remote_mb) : "memory");
}
__device__ __forceinline__ void mbar_wait_cluster(uint32_t mb, uint32_t parity) {
    uint32_t done;
    asm volatile(
        "{ .reg .pred p; mbarrier.try_wait.parity.acquire.cluster.shared::cta.b64 p, [%1], %2;\n\t"
        "selp.b32 %0, 1, 0, p; }"
        : "=r"(done) : "r"(mb), "r"(parity) : "memory");
    if (!done) {
        asm volatile(
            "{ .reg .pred P1;\n\t"
            "WL_%=: mbarrier.try_wait.parity.acquire.cluster.shared::cta.b64 P1, [%0], %1, 0x989680;\n\t"
            "@P1 bra.uni WD_%=;\n\t"
            "bra.uni WL_%=;\n\t"
            "WD_%=: }"
            :: "r"(mb), "r"(parity) : "memory");
    }
}
#define MBAR_INIT(mb, cnt) \
    asm volatile("mbarrier.init.shared.b64 [%0], %1;" :: "r"(mb), "r"((uint32_t)(cnt)) : "memory")
#define CLUSTER_SYNC_() do { \
    asm volatile("barrier.cluster.arrive.aligned;" ::: "memory"); \
    asm volatile("barrier.cluster.wait.aligned;" ::: "memory"); \
} while (0)

// -------------------- tensor-core primitives --------------------------------
__device__ __forceinline__ void ldmat4(uint32_t* r, uint32_t addr) {
    asm volatile("ldmatrix.sync.aligned.m8n8.x4.shared.b16 {%0,%1,%2,%3}, [%4];"
        : "=r"(r[0]), "=r"(r[1]), "=r"(r[2]), "=r"(r[3]) : "r"(addr));
}
__device__ __forceinline__ void mma16816(float* c, const uint32_t* a, const uint32_t* b) {
    asm volatile(
        "mma.sync.aligned.m16n8k16.row.col.f32.bf16.bf16.f32 "
        "{%0,%1,%2,%3}, {%4,%5,%6,%7}, {%8,%9}, {%0,%1,%2,%3};"
        : "+f"(c[0]), "+f"(c[1]), "+f"(c[2]), "+f"(c[3])
        : "r"(a[0]), "r"(a[1]), "r"(a[2]), "r"(a[3]), "r"(b[0]), "r"(b[1]));
}

// ---------------------------------------------------------------------------
// split_bf16: x -> (hi, lo) bf16
// ---------------------------------------------------------------------------
__global__ __launch_bounds__(256) void split_bf16(
    const float* __restrict__ x, __nv_bfloat16* __restrict__ hi,
    __nv_bfloat16* __restrict__ lo, int n4)
{
    int i = blockIdx.x * 256 + threadIdx.x;
    if (i >= n4) return;
    float4 v = ((const float4*)x)[i];
    __nv_bfloat16 h0 = __float2bfloat16(v.x), h1 = __float2bfloat16(v.y);
    __nv_bfloat16 h2 = __float2bfloat16(v.z), h3 = __float2bfloat16(v.w);
    __nv_bfloat16 l0 = __float2bfloat16(v.x - __bfloat162float(h0));
    __nv_bfloat16 l1 = __float2bfloat16(v.y - __bfloat162float(h1));
    __nv_bfloat16 l2 = __float2bfloat16(v.z - __bfloat162float(h2));
    __nv_bfloat16 l3 = __float2bfloat16(v.w - __bfloat162float(h3));
    ((__nv_bfloat162*)hi)[2 * i + 0] = __nv_bfloat162(h0, h1);
    ((__nv_bfloat162*)hi)[2 * i + 1] = __nv_bfloat162(h2, h3);
    ((__nv_bfloat162*)lo)[2 * i + 0] = __nv_bfloat162(l0, l1);
    ((__nv_bfloat162*)lo)[2 * i + 1] = __nv_bfloat162(l2, l3);
}

// ---------------------------------------------------------------------------
// wsplit_t: W[K][N] fp32 -> Wt hi/lo [N][K] bf16
// ---------------------------------------------------------------------------
__global__ void wsplit_t(const float* __restrict__ W,
                         __nv_bfloat16* __restrict__ Th,
                         __nv_bfloat16* __restrict__ Tl, int K, int N)
{
    __shared__ float tile[32][33];
    int n0 = blockIdx.x * 32, k0 = blockIdx.y * 32;
    int tx = threadIdx.x, ty = threadIdx.y;
#pragma unroll
    for (int j = 0; j < 32; j += 8)
        tile[ty + j][tx] = W[(size_t)(k0 + ty + j) * N + n0 + tx];
    __syncthreads();
#pragma unroll
    for (int j = 0; j < 32; j += 8) {
        float v = tile[tx][ty + j];
        __nv_bfloat16 h = __float2bfloat16(v);
        __nv_bfloat16 l = __float2bfloat16(v - __bfloat162float(h));
        Th[(size_t)(n0 + ty + j) * K + k0 + tx] = h;
        Tl[(size_t)(n0 + ty + j) * K + k0 + tx] = l;
    }
}

// ---------------------------------------------------------------------------
// gemm_mma_split (round-6 proven)
// ---------------------------------------------------------------------------
__global__ __launch_bounds__(256, 2) void gemm_mma_split(
    const __nv_bfloat16* __restrict__ Ahi, const __nv_bfloat16* __restrict__ Alo,
    const __nv_bfloat16* __restrict__ Bhi, const __nv_bfloat16* __restrict__ Blo,
    const float* __restrict__ bias, float* __restrict__ C,
    int M, int N, int K)
{
    __shared__ __nv_bfloat16 sAh[128][40], sAl[128][40], sBh[128][40], sBl[128][40];

    int tid = threadIdx.x;
    int wid = tid >> 5, lid = tid & 31;
    int wm = wid >> 2, wn = wid & 3;
    int g  = lid >> 2, tg = lid & 3;
    int lj = lid >> 3, lr = lid & 7;
    int bn = blockIdx.x * 128;
    int bm = blockIdx.y * 128;

    float acc[4][4][4];
#pragma unroll
    for (int mt = 0; mt < 4; mt++)
#pragma unroll
        for (int nt = 0; nt < 4; nt++)
#pragma unroll
            for (int q = 0; q < 4; q++) acc[mt][nt][q] = 0.f;

    uint32_t baseAh = smem_u32(&sAh[0][0]), baseAl = smem_u32(&sAl[0][0]);
    uint32_t baseBh = smem_u32(&sBh[0][0]), baseBl = smem_u32(&sBl[0][0]);

    int aRowL = wm * 64 + (lj & 1) * 8 + lr;
    int aColL = (lj >> 1) * 8;
    int bRowL = wn * 32 + (lj >> 1) * 8 + lr;
    int bColL = (lj & 1) * 8;

    for (int kc = 0; kc < K; kc += 32) {
        __syncthreads();
        for (int i = tid; i < 512; i += 256) {
            int r = i >> 2, u = (i & 3) * 8;
            size_t ga = (size_t)(bm + r) * K + kc + u;
            size_t gb = (size_t)(bn + r) * K + kc + u;
            *(uint4*)&sAh[r][u] = *(const uint4*)&Ahi[ga];
            *(uint4*)&sAl[r][u] = *(const uint4*)&Alo[ga];
            *(uint4*)&sBh[r][u] = *(const uint4*)&Bhi[gb];
            *(uint4*)&sBl[r][u] = *(const uint4*)&Blo[gb];
        }
        __syncthreads();

#pragma unroll
        for (int ks2 = 0; ks2 < 32; ks2 += 16) {
            uint32_t bh[2][4], bl[2][4];
#pragma unroll
            for (int ntp = 0; ntp < 2; ntp++) {
                uint32_t off = (uint32_t)((bRowL + ntp * 16) * 40 + ks2 + bColL) * 2;
                ldmat4(bh[ntp], baseBh + off);
                ldmat4(bl[ntp], baseBl + off);
            }
#pragma unroll
            for (int mt = 0; mt < 4; mt++) {
                uint32_t ah[4], al[4];
                uint32_t off = (uint32_t)((aRowL + mt * 16) * 40 + ks2 + aColL) * 2;
                ldmat4(ah, baseAh + off);
                ldmat4(al, baseAl + off);
#pragma unroll
                for (int nt = 0; nt < 4; nt++) {
                    const uint32_t* pbh = &bh[nt >> 1][(nt & 1) * 2];
                    const uint32_t* pbl = &bl[nt >> 1][(nt & 1) * 2];
                    mma16816(acc[mt][nt], ah, pbh);
                    mma16816(acc[mt][nt], ah, pbl);
                    mma16816(acc[mt][nt], al, pbh);
                }
            }
        }
    }

#pragma unroll
    for (int mt = 0; mt < 4; mt++) {
#pragma unroll
        for (int nt = 0; nt < 4; nt++) {
            int row = bm + wm * 64 + mt * 16 + g;
            int col = bn + wn * 32 + nt * 8 + tg * 2;
            float b0 = __ldg(&bias[col]), b1 = __ldg(&bias[col + 1]);
            float2 v0 = make_float2(acc[mt][nt][0] + b0, acc[mt][nt][1] + b1);
            float2 v1 = make_float2(acc[mt][nt][2] + b0, acc[mt][nt][3] + b1);
            *(float2*)&C[(size_t)row * N + col]       = v0;
            *(float2*)&C[(size_t)(row + 8) * N + col] = v1;
        }
    }
}

// ---------------------------------------------------------------------------
// lstm_rec_dsm2: cluster of 16 CTAs = one batch group (Bg=8 rows).
// Gate threads write h slice into local staging; 16 sender threads each push
// the full 512B/256B slice to ONE destination CTA via st.shared::cluster.v4
// and then arrive (release) on that destination's phase mbarrier. Count=16.
// ---------------------------------------------------------------------------
template <int H, int SL, int KP, int CB, int RS>
__global__ __launch_bounds__(256, 1) void lstm_rec_dsm2(
    const float* __restrict__ zx, const float* __restrict__ U,
    float* __restrict__ out)
{
    constexpr int N4   = 4 * H;
    constexpr int Bg   = 8;
    constexpr int NH   = H / 16;
    constexpr int NCZ  = 4 * NH;
    constexpr int K2   = H / 2;
    constexpr int CW   = 4;
    constexpr int RT   = Bg / RS;
    constexpr int NRED = Bg * NH;
    constexpr int HB   = Bg * H;            // floats per h buffer
    constexpr int NV   = NH / 4;            // v4 chunks per row (4 or 2)
    static_assert(SL * KP == K2 && CB * CW == NCZ && SL * CB * RS == 256, "split");

    extern __shared__ float dynsm[];
    float* hb  = dynsm;                     // [2][Bg][H]
    float* zp  = hb + 2 * HB;               // [SL][Bg][NCZ]
    float* stg = zp + SL * Bg * NCZ;        // [Bg][NH] staging
    __shared__ __align__(8) ull mbar[2];

    int tid = threadIdx.x;
    int g   = blockIdx.x >> 4;
    int cb  = blockIdx.x & 15;              // == cluster rank
    int jb  = cb * NH;

    uint32_t hb_u   = smem_u32(hb);
    uint32_t mbar_u = smem_u32(&mbar[0]);

    if (tid == 0) { MBAR_INIT(mbar_u, 16); MBAR_INIT(mbar_u + 8, 16); }
    CLUSTER_SYNC_();                        // peers' init visible before sends

    // thread decomposition (matmul)
    int s   = tid / (CB * RS);
    int rem = tid % (CB * RS);
    int cb2 = rem / RS;
    int rs  = rem % RS;

    // U slice -> registers (one-time)
    ull Ureg[KP][CW];
#pragma unroll
    for (int kk = 0; kk < KP; kk++)
#pragma unroll
        for (int cw = 0; cw < CW; cw++) {
            int c    = cb2 * CW + cw;
            int gi   = c / NH;
            int j    = c % NH;
            int gcol = gi * H + jb + j;
            int k2   = s * KP + kk;
            Ureg[kk][cw] = pack2(__ldg(&U[(size_t)(2 * k2) * N4 + gcol]),
                                 __ldg(&U[(size_t)(2 * k2 + 1) * N4 + gcol]));
        }

    // reduce identity (tid < NRED)
    int rr = tid / NH;
    int jj = tid % NH;
    int bglob = g * Bg + rr;
    float creg = 0.f;

    // Sender identity (tid < 16): dest CTA = tid; precompute remote addresses.
    uint32_t dslice = 0, dmb0 = 0, dmb1 = 0;
    if (tid < 16) {
        dslice = mapa_u32(hb_u + (uint32_t)jb * 4u, (uint32_t)tid);  // buffer 0, our cols
        dmb0   = mapa_u32(mbar_u,     (uint32_t)tid);
        dmb1   = mapa_u32(mbar_u + 8, (uint32_t)tid);
    }

    for (int t = 0; t < T_STEPS; t++) {
        // Prefetch zx (overlaps the wait).
        float zx0 = 0.f, zx1 = 0.f, zx2 = 0.f, zx3 = 0.f;
        if (tid < NRED) {
            size_t basei = ((size_t)bglob * T_STEPS + t) * N4 + jb + jj;
            zx0 = zx[basei + 0 * (size_t)H];
            zx1 = zx[basei + 1 * (size_t)H];
            zx2 = zx[basei + 2 * (size_t)H];
            zx3 = zx[basei + 3 * (size_t)H];
        }

        float z0 = 0.f, z1 = 0.f, z2 = 0.f, z3 = 0.f;
        if (t > 0) {
            int pb = (t - 1) & 1;
            mbar_wait_cluster(mbar_u + 8 * pb, ((t - 1) >> 1) & 1);

            const ull* h2 = (const ull*)(hb + pb * HB);  // [Bg][K2]

            ull acc[RT][CW];
#pragma unroll
            for (int i = 0; i < RT; i++)
#pragma unroll
                for (int cw = 0; cw < CW; cw++) acc[i][cw] = 0ull;

#pragma unroll
            for (int kk = 0; kk < KP; kk++) {
                int k2 = s * KP + kk;
                ull hv[RT];
#pragma unroll
                for (int i = 0; i < RT; i++)
                    hv[i] = h2[(rs * RT + i) * K2 + k2];
#pragma unroll
                for (int i = 0; i < RT; i++)
#pragma unroll
                    for (int cw = 0; cw < CW; cw++)
                        acc[i][cw] = ffma2(hv[i], Ureg[kk][cw], acc[i][cw]);
            }
#pragma unroll
            for (int i = 0; i < RT; i++) {
                float4 v;
                v.x = sum2(acc[i][0]);
                v.y = sum2(acc[i][1]);
                v.z = sum2(acc[i][2]);
                v.w = sum2(acc[i][3]);
                *(float4*)&zp[(s * Bg + rs * RT + i) * NCZ + cb2 * CW] = v;
            }
            __syncthreads();                               // B1: zp ready

            if (tid < NRED) {
#pragma unroll
                for (int s2 = 0; s2 < SL; s2++) {
                    const float* zr = &zp[(s2 * Bg + rr) * NCZ];
                    z0 += zr[0 * NH + jj];
                    z1 += zr[1 * NH + jj];
                    z2 += zr[2 * NH + jj];
                    z3 += zr[3 * NH + jj];
                }
            }
        }

        // Gates + state update; write h to global out + local staging.
        bool publish = (t < T_STEPS - 1);
        if (tid < NRED) {
            float zi = zx0 + z0, zf = zx1 + z1, zg = zx2 + z2, zo = zx3 + z3;
            float si = 1.f / (1.f + __expf(-zi));
            float sf = 1.f / (1.f + __expf(-zf));
            float so = 1.f / (1.f + __expf(-zo));
            float gg = zg > 0.f ? zg : 0.f;
            creg = sf * creg + si * gg;
            float cr = creg > 0.f ? creg : 0.f;
            float hval = so * cr;
            out[((size_t)bglob * T_STEPS + t) * H + jb + jj] = hval;
            stg[rr * NH + jj] = hval;
        }
        __syncthreads();                                   // B2: staging ready,
                                                           //     matmul reads done
        if (publish && tid < 16) {
            uint32_t boff = (uint32_t)((t & 1) * (int)(HB * 4));
#pragma unroll
            for (int r = 0; r < Bg; r++) {
#pragma unroll
                for (int q = 0; q < NV; q++) {
                    float4 v = *(float4*)&stg[r * NH + q * 4];
                    st_cluster_v4(dslice + boff + (uint32_t)((r * H + q * 4) * 4), v);
                }
            }
            // Release-arrive on the destination's phase barrier: orders THIS
            // thread's remote stores for the consumer's acquire.
            mbar_arrive_remote((t & 1) ? dmb1 : dmb0);
        }
        __syncthreads();                                   // B3: staging protected
    }

    // No CTA may exit while peers might still address our smem.
    CLUSTER_SYNC_();
}

// ---------------------------------------------------------------------------
// lstm_rec_flag: round-6 proven fallback (L2 flag sync).
// ---------------------------------------------------------------------------
template <int H, int SL, int KP, int CB, int RS>
__global__ __launch_bounds__(256, 1) void lstm_rec_flag(
    const float* __restrict__ zx, const float* __restrict__ U,
    float* __restrict__ out, int* __restrict__ flags)
{
    constexpr int N4   = 4 * H;
    constexpr int Bg   = 8;
    constexpr int Pc   = 16;
    constexpr int NH   = H / Pc;
    constexpr int NCZ  = 4 * NH;
    constexpr int K2   = H / 2;
    constexpr int CW   = 4;
    constexpr int RT   = Bg / RS;
    constexpr int NRED = Bg * NH;
    static_assert(SL * KP == K2 && CB * CW == NCZ && SL * CB * RS == 256, "split");

    __shared__ ull   h2[Bg * K2];
    __shared__ float zp[SL * Bg * NCZ];
    float* h_s = (float*)h2;

    int tid = threadIdx.x;
    int g   = blockIdx.x >> 4;
    int cb  = blockIdx.x & 15;
    int jb  = cb * NH;

    int s   = tid / (CB * RS);
    int rem = tid % (CB * RS);
    int cb2 = rem / RS;
    int rs  = rem % RS;

    ull Ureg[KP][CW];
#pragma unroll
    for (int kk = 0; kk < KP; kk++)
#pragma unroll
        for (int cw = 0; cw < CW; cw++) {
            int c    = cb2 * CW + cw;
            int gi   = c / NH;
            int j    = c % NH;
            int gcol = gi * H + jb + j;
            int k2   = s * KP + kk;
            Ureg[kk][cw] = pack2(__ldg(&U[(size_t)(2 * k2) * N4 + gcol]),
                                 __ldg(&U[(size_t)(2 * k2 + 1) * N4 + gcol]));
        }

    int rr = tid / NH;
    int jj = tid % NH;
    int bglob = g * Bg + rr;
    float creg = 0.f;

    int* flagrd = flags + g * T_STEPS;
    __syncthreads();

    for (int t = 0; t < T_STEPS; t++) {
        float zx0 = 0.f, zx1 = 0.f, zx2 = 0.f, zx3 = 0.f;
        if (tid < NRED) {
            size_t basei = ((size_t)bglob * T_STEPS + t) * N4 + jb + jj;
            zx0 = zx[basei + 0 * (size_t)H];
            zx1 = zx[basei + 1 * (size_t)H];
            zx2 = zx[basei + 2 * (size_t)H];
            zx3 = zx[basei + 3 * (size_t)H];
        }

        float z0 = 0.f, z1 = 0.f, z2 = 0.f, z3 = 0.f;
        if (t > 0) {
            if (tid == 0) {
                while (ld_acquire_gpu(&flagrd[t - 1]) < Pc) { }
            }
            __syncthreads();

            for (int i4 = tid; i4 < (Bg * H) / 4; i4 += 256) {
                int idx = i4 * 4;
                int r = idx / H, k = idx % H;
                *(float4*)&h_s[idx] =
                    *(const float4*)&out[((size_t)(g * Bg + r) * T_STEPS + (t - 1)) * H + k];
            }
            __syncthreads();

            ull acc[RT][CW];
#pragma unroll
            for (int i = 0; i < RT; i++)
#pragma unroll
                for (int cw = 0; cw < CW; cw++) acc[i][cw] = 0ull;

#pragma unroll
            for (int kk = 0; kk < KP; kk++) {
                int k2 = s * KP + kk;
                ull hv[RT];
#pragma unroll
                for (int i = 0; i < RT; i++)
                    hv[i] = h2[(rs * RT + i) * K2 + k2];
#pragma unroll
                for (int i = 0; i < RT; i++)
#pragma unroll
                    for (int cw = 0; cw < CW; cw++)
                        acc[i][cw] = ffma2(hv[i], Ureg[kk][cw], acc[i][cw]);
            }
#pragma unroll
            for (int i = 0; i < RT; i++) {
                float4 v;
                v.x = sum2(acc[i][0]);
                v.y = sum2(acc[i][1]);
                v.z = sum2(acc[i][2]);
                v.w = sum2(acc[i][3]);
                *(float4*)&zp[(s * Bg + rs * RT + i) * NCZ + cb2 * CW] = v;
            }
            __syncthreads();

            if (tid < NRED) {
#pragma unroll
                for (int s2 = 0; s2 < SL; s2++) {
                    const float* zr = &zp[(s2 * Bg + rr) * NCZ];
                    z0 += zr[0 * NH + jj];
                    z1 += zr[1 * NH + jj];
                    z2 += zr[2 * NH + jj];
                    z3 += zr[3 * NH + jj];
                }
            }
        }

        if (tid < NRED) {
            float zi = zx0 + z0, zf = zx1 + z1, zg = zx2 + z2, zo = zx3 + z3;
            float si = 1.f / (1.f + __expf(-zi));
            float sf = 1.f / (1.f + __expf(-zf));
            float so = 1.f / (1.f + __expf(-zo));
            float gg = zg > 0.f ? zg : 0.f;
            creg = sf * creg + si * gg;
            float cr = creg > 0.f ? creg : 0.f;
            out[((size_t)bglob * T_STEPS + t) * H + jb + jj] = so * cr;
        }
        __syncthreads();
        if (tid == 0) red_release_gpu_add(&flags[g * T_STEPS + t], 1);
    }
}

// ---------------------------------------------------------------------------
extern "C" void kernel_launch(void* const* d_in, const int* in_sizes, int n_in,
                              void* d_out, int out_size)
{
    const float* x  = (const float*)d_in[0];
    const float* W1 = (const float*)d_in[1];
    const float* U1 = (const float*)d_in[2];
    const float* b1 = (const float*)d_in[3];
    const float* W2 = (const float*)d_in[4];
    const float* U2 = (const float*)d_in[5];
    const float* b2 = (const float*)d_in[6];
    const float* W3 = (const float*)d_in[7];
    const float* U3 = (const float*)d_in[8];
    const float* b3 = (const float*)d_in[9];
    const float* W4 = (const float*)d_in[10];
    const float* U4 = (const float*)d_in[11];
    const float* b4 = (const float*)d_in[12];
    float* out = (float*)d_out;

    void *p;
    cudaGetSymbolAddress(&p, g_zx);    float* zx    = (float*)p;
    cudaGetSymbolAddress(&p, g_bufA);  float* bufA  = (float*)p;
    cudaGetSymbolAddress(&p, g_bufB);  float* bufB  = (float*)p;
    cudaGetSymbolAddress(&p, g_flags); int*   flags = (int*)p;
    cudaGetSymbolAddress(&p, g_ahi);   __nv_bfloat16* ahi  = (__nv_bfloat16*)p;
    cudaGetSymbolAddress(&p, g_alo);   __nv_bfloat16* alo  = (__nv_bfloat16*)p;
    cudaGetSymbolAddress(&p, g_wthi);  __nv_bfloat16* wthi = (__nv_bfloat16*)p;
    cudaGetSymbolAddress(&p, g_wtlo);  __nv_bfloat16* wtlo = (__nv_bfloat16*)p;

    const int M = BATCH * T_STEPS;  // 65536

    // dyn smem: hb (2*Bg*H) + zp (SL*Bg*NCZ) + staging (Bg*NH), floats
    const int DSM256 = (2 * 8 * 256 + 16 * 8 * 64 + 8 * 16) * 4;  // 49664
    const int DSM128 = (2 * 8 * 128 + 8 * 8 * 32 + 8 * 8) * 4;    // 16640

    auto* k256 = lstm_rec_dsm2<256, 16, 8, 16, 1>;
    auto* k128 = lstm_rec_dsm2<128, 8, 8, 8, 4>;
    cudaFuncSetAttribute(k256, cudaFuncAttributeMaxDynamicSharedMemorySize, DSM256);
    cudaFuncSetAttribute(k256, cudaFuncAttributeNonPortableClusterSizeAllowed, 1);
    cudaFuncSetAttribute(k128, cudaFuncAttributeMaxDynamicSharedMemorySize, DSM128);
    cudaFuncSetAttribute(k128, cudaFuncAttributeNonPortableClusterSizeAllowed, 1);

    cudaLaunchAttribute cattr[1];
    cattr[0].id = cudaLaunchAttributeClusterDimension;
    cattr[0].val.clusterDim = {16, 1, 1};

    cudaLaunchConfig_t cfg256 = {};
    cfg256.gridDim = {128, 1, 1};
    cfg256.blockDim = {256, 1, 1};
    cfg256.dynamicSmemBytes = DSM256;
    cfg256.attrs = cattr;
    cfg256.numAttrs = 1;

    cudaLaunchConfig_t cfg128 = cfg256;
    cfg128.dynamicSmemBytes = DSM128;

    int nclu = 0;
    cudaError_t e = cudaOccupancyMaxActiveClusters(&nclu, k256, &cfg256);
    bool use_dsmem = (e == cudaSuccess && nclu >= 1);
    if (use_dsmem) {
        int nclu2 = 0;
        e = cudaOccupancyMaxActiveClusters(&nclu2, k128, &cfg128);
        use_dsmem = (e == cudaSuccess && nclu2 >= 1);
    }
    cudaGetLastError();

    cudaMemsetAsync(flags, 0, 4 * 8 * T_STEPS * sizeof(int));

    // ---- Layer 1: F=256 -> H=256 ----
    split_bf16<<<M * 256 / 4 / 256, 256>>>(x, ahi, alo, M * 256 / 4);
    wsplit_t<<<dim3(1024 / 32, 256 / 32), dim3(32, 8)>>>(W1, wthi, wtlo, 256, 1024);
    gemm_mma_split<<<dim3(8, M / 128), 256>>>(ahi, alo, wthi, wtlo, b1, zx, M, 1024, 256);
    if (use_dsmem) cudaLaunchKernelEx(&cfg256, k256, (const float*)zx, U1, bufA);
    else lstm_rec_flag<256, 16, 8, 16, 1><<<128, 256>>>(zx, U1, bufA, flags + 0 * 8 * T_STEPS);

    // ---- Layer 2: F=256 -> H=128 ----
    split_bf16<<<M * 256 / 4 / 256, 256>>>(bufA, ahi, alo, M * 256 / 4);
    wsplit_t<<<dim3(512 / 32, 256 / 32), dim3(32, 8)>>>(W2, wthi, wtlo, 256, 512);
    gemm_mma_split<<<dim3(4, M / 128), 256>>>(ahi, alo, wthi, wtlo, b2, zx, M, 512, 256);
    if (use_dsmem) cudaLaunchKernelEx(&cfg128, k128, (const float*)zx, U2, bufB);
    else lstm_rec_flag<128, 8, 8, 8, 4><<<128, 256>>>(zx, U2, bufB, flags + 1 * 8 * T_STEPS);

    // ---- Layer 3: F=128 -> H=256 ----
    split_bf16<<<M * 128 / 4 / 256, 256>>>(bufB, ahi, alo, M * 128 / 4);
    wsplit_t<<<dim3(1024 / 32, 128 / 32), dim3(32, 8)>>>(W3, wthi, wtlo, 128, 1024);
    gemm_mma_split<<<dim3(8, M / 128), 256>>>(ahi, alo, wthi, wtlo, b3, zx, M, 1024, 128);
    if (use_dsmem) cudaLaunchKernelEx(&cfg256, k256, (const float*)zx, U3, bufA);
    else lstm_rec_flag<256, 16, 8, 16, 1><<<128, 256>>>(zx, U3, bufA, flags + 2 * 8 * T_STEPS);

    // ---- Layer 4: F=256 -> H=256 ----
    split_bf16<<<M * 256 / 4 / 256, 256>>>(bufA, ahi, alo, M * 256 / 4);
    wsplit_t<<<dim3(1024 / 32, 256 / 32), dim3(32, 8)>>>(W4, wthi, wtlo, 256, 1024);
    gemm_mma_split<<<dim3(8, M / 128), 256>>>(ahi, alo, wthi, wtlo, b4, zx, M, 1024, 256);
    if (use_dsmem) cudaLaunchKernelEx(&cfg256, k256, (const float*)zx, U4, out);
    else lstm_rec_flag<256, 16, 8, 16, 1><<<128, 256>>>(zx, U4, out, flags + 3 * 8 * T_STEPS);
}

// round 14
// speedup vs baseline: 1.8918x; 1.8175x over previous
#include <cuda_runtime.h>
#include <cuda_bf16.h>
#include <cstdint>

typedef unsigned long long ull;

// ---------------------------------------------------------------------------
// LSTM autoencoder: 4 layers, B=64, T=1024, H in {256,128,256,256}.
//   zx GEMMs: mma.sync bf16 split-precision (hi/lo, 3 products, fp32 accum)
//   recurrence: persistent 128-CTA kernel, 8 groups x 16 col CTAs, with
//     PER-PRODUCER flags + per-slice overlap:
//       - matmul k-slices align 1:1 with producer CTAs' h chunks
//       - each half-warp waits only on ITS producer, loads 512B chunk,
//         computes its zp partial; slices overlap waiting & compute
//       - compact double-buffered hx exchange buffer (L2)
//     No clusters, no DSMEM (measured slower), no counters.
// ---------------------------------------------------------------------------

#define T_STEPS 1024
#define BATCH   64

__device__ float g_zx[67108864];                // [B*T][4*256] max
__device__ float g_bufA[16777216];              // [B][T][256]
__device__ float g_bufB[8388608];               // [B][T][128]
__device__ int   g_flags[4 * 8 * T_STEPS * 16]; // [layer][G][T][16]
__device__ float g_hx[8 * 2 * 16 * 128];        // [G][parity][cb][CHK<=128]
__device__ __nv_bfloat16 g_ahi[16777216];       // A hi  [M][K]
__device__ __nv_bfloat16 g_alo[16777216];       // A lo
__device__ __nv_bfloat16 g_wthi[262144];        // W^T hi [N][K]
__device__ __nv_bfloat16 g_wtlo[262144];        // W^T lo

// -------------------- scalar primitives ------------------------------------
__device__ __forceinline__ int ld_acquire_gpu(const int* p) {
    int v;
    asm volatile("ld.acquire.gpu.global.s32 %0, [%1];" : "=r"(v) : "l"(p) : "memory");
    return v;
}
__device__ __forceinline__ void red_release_gpu_add(int* p, int v) {
    asm volatile("red.release.gpu.global.add.s32 [%0], %1;" :: "l"(p), "r"(v) : "memory");
}
__device__ __forceinline__ ull pack2(float x, float y) {
    ull r; asm("mov.b64 %0, {%1, %2};" : "=l"(r) : "f"(x), "f"(y)); return r;
}
__device__ __forceinline__ ull ffma2(ull a, ull b, ull c) {
    ull d; asm("fma.rn.f32x2 %0, %1, %2, %3;" : "=l"(d) : "l"(a), "l"(b), "l"(c)); return d;
}
__device__ __forceinline__ float sum2(ull a) {
    float x, y; asm("mov.b64 {%0, %1}, %2;" : "=f"(x), "=f"(y) : "l"(a)); return x + y;
}
__device__ __forceinline__ uint32_t smem_u32(const void* p) {
    uint32_t a;
    asm("{ .reg .u64 t; cvta.to.shared.u64 t, %1; cvt.u32.u64 %0, t; }" : "=r"(a) : "l"(p));
    return a;
}

// -------------------- tensor-core primitives --------------------------------
__device__ __forceinline__ void ldmat4(uint32_t* r, uint32_t addr) {
    asm volatile("ldmatrix.sync.aligned.m8n8.x4.shared.b16 {%0,%1,%2,%3}, [%4];"
        : "=r"(r[0]), "=r"(r[1]), "=r"(r[2]), "=r"(r[3]) : "r"(addr));
}
__device__ __forceinline__ void mma16816(float* c, const uint32_t* a, const uint32_t* b) {
    asm volatile(
        "mma.sync.aligned.m16n8k16.row.col.f32.bf16.bf16.f32 "
        "{%0,%1,%2,%3}, {%4,%5,%6,%7}, {%8,%9}, {%0,%1,%2,%3};"
        : "+f"(c[0]), "+f"(c[1]), "+f"(c[2]), "+f"(c[3])
        : "r"(a[0]), "r"(a[1]), "r"(a[2]), "r"(a[3]), "r"(b[0]), "r"(b[1]));
}

// ---------------------------------------------------------------------------
// split_bf16: x -> (hi, lo) bf16
// ---------------------------------------------------------------------------
__global__ __launch_bounds__(256) void split_bf16(
    const float* __restrict__ x, __nv_bfloat16* __restrict__ hi,
    __nv_bfloat16* __restrict__ lo, int n4)
{
    int i = blockIdx.x * 256 + threadIdx.x;
    if (i >= n4) return;
    float4 v = ((const float4*)x)[i];
    __nv_bfloat16 h0 = __float2bfloat16(v.x), h1 = __float2bfloat16(v.y);
    __nv_bfloat16 h2 = __float2bfloat16(v.z), h3 = __float2bfloat16(v.w);
    __nv_bfloat16 l0 = __float2bfloat16(v.x - __bfloat162float(h0));
    __nv_bfloat16 l1 = __float2bfloat16(v.y - __bfloat162float(h1));
    __nv_bfloat16 l2 = __float2bfloat16(v.z - __bfloat162float(h2));
    __nv_bfloat16 l3 = __float2bfloat16(v.w - __bfloat162float(h3));
    ((__nv_bfloat162*)hi)[2 * i + 0] = __nv_bfloat162(h0, h1);
    ((__nv_bfloat162*)hi)[2 * i + 1] = __nv_bfloat162(h2, h3);
    ((__nv_bfloat162*)lo)[2 * i + 0] = __nv_bfloat162(l0, l1);
    ((__nv_bfloat162*)lo)[2 * i + 1] = __nv_bfloat162(l2, l3);
}

// ---------------------------------------------------------------------------
// wsplit_t: W[K][N] fp32 -> Wt hi/lo [N][K] bf16
// ---------------------------------------------------------------------------
__global__ void wsplit_t(const float* __restrict__ W,
                         __nv_bfloat16* __restrict__ Th,
                         __nv_bfloat16* __restrict__ Tl, int K, int N)
{
    __shared__ float tile[32][33];
    int n0 = blockIdx.x * 32, k0 = blockIdx.y * 32;
    int tx = threadIdx.x, ty = threadIdx.y;
#pragma unroll
    for (int j = 0; j < 32; j += 8)
        tile[ty + j][tx] = W[(size_t)(k0 + ty + j) * N + n0 + tx];
    __syncthreads();
#pragma unroll
    for (int j = 0; j < 32; j += 8) {
        float v = tile[tx][ty + j];
        __nv_bfloat16 h = __float2bfloat16(v);
        __nv_bfloat16 l = __float2bfloat16(v - __bfloat162float(h));
        Th[(size_t)(n0 + ty + j) * K + k0 + tx] = h;
        Tl[(size_t)(n0 + ty + j) * K + k0 + tx] = l;
    }
}

// ---------------------------------------------------------------------------
// gemm_mma_split (round-6 proven)
// ---------------------------------------------------------------------------
__global__ __launch_bounds__(256, 2) void gemm_mma_split(
    const __nv_bfloat16* __restrict__ Ahi, const __nv_bfloat16* __restrict__ Alo,
    const __nv_bfloat16* __restrict__ Bhi, const __nv_bfloat16* __restrict__ Blo,
    const float* __restrict__ bias, float* __restrict__ C,
    int M, int N, int K)
{
    __shared__ __nv_bfloat16 sAh[128][40], sAl[128][40], sBh[128][40], sBl[128][40];

    int tid = threadIdx.x;
    int wid = tid >> 5, lid = tid & 31;
    int wm = wid >> 2, wn = wid & 3;
    int g  = lid >> 2, tg = lid & 3;
    int lj = lid >> 3, lr = lid & 7;
    int bn = blockIdx.x * 128;
    int bm = blockIdx.y * 128;

    float acc[4][4][4];
#pragma unroll
    for (int mt = 0; mt < 4; mt++)
#pragma unroll
        for (int nt = 0; nt < 4; nt++)
#pragma unroll
            for (int q = 0; q < 4; q++) acc[mt][nt][q] = 0.f;

    uint32_t baseAh = smem_u32(&sAh[0][0]), baseAl = smem_u32(&sAl[0][0]);
    uint32_t baseBh = smem_u32(&sBh[0][0]), baseBl = smem_u32(&sBl[0][0]);

    int aRowL = wm * 64 + (lj & 1) * 8 + lr;
    int aColL = (lj >> 1) * 8;
    int bRowL = wn * 32 + (lj >> 1) * 8 + lr;
    int bColL = (lj & 1) * 8;

    for (int kc = 0; kc < K; kc += 32) {
        __syncthreads();
        for (int i = tid; i < 512; i += 256) {
            int r = i >> 2, u = (i & 3) * 8;
            size_t ga = (size_t)(bm + r) * K + kc + u;
            size_t gb = (size_t)(bn + r) * K + kc + u;
            *(uint4*)&sAh[r][u] = *(const uint4*)&Ahi[ga];
            *(uint4*)&sAl[r][u] = *(const uint4*)&Alo[ga];
            *(uint4*)&sBh[r][u] = *(const uint4*)&Bhi[gb];
            *(uint4*)&sBl[r][u] = *(const uint4*)&Blo[gb];
        }
        __syncthreads();

#pragma unroll
        for (int ks2 = 0; ks2 < 32; ks2 += 16) {
            uint32_t bh[2][4], bl[2][4];
#pragma unroll
            for (int ntp = 0; ntp < 2; ntp++) {
                uint32_t off = (uint32_t)((bRowL + ntp * 16) * 40 + ks2 + bColL) * 2;
                ldmat4(bh[ntp], baseBh + off);
                ldmat4(bl[ntp], baseBl + off);
            }
#pragma unroll
            for (int mt = 0; mt < 4; mt++) {
                uint32_t ah[4], al[4];
                uint32_t off = (uint32_t)((aRowL + mt * 16) * 40 + ks2 + aColL) * 2;
                ldmat4(ah, baseAh + off);
                ldmat4(al, baseAl + off);
#pragma unroll
                for (int nt = 0; nt < 4; nt++) {
                    const uint32_t* pbh = &bh[nt >> 1][(nt & 1) * 2];
                    const uint32_t* pbl = &bl[nt >> 1][(nt & 1) * 2];
                    mma16816(acc[mt][nt], ah, pbh);
                    mma16816(acc[mt][nt], ah, pbl);
                    mma16816(acc[mt][nt], al, pbh);
                }
            }
        }
    }

#pragma unroll
    for (int mt = 0; mt < 4; mt++) {
#pragma unroll
        for (int nt = 0; nt < 4; nt++) {
            int row = bm + wm * 64 + mt * 16 + g;
            int col = bn + wn * 32 + nt * 8 + tg * 2;
            float b0 = __ldg(&bias[col]), b1 = __ldg(&bias[col + 1]);
            float2 v0 = make_float2(acc[mt][nt][0] + b0, acc[mt][nt][1] + b1);
            float2 v1 = make_float2(acc[mt][nt][2] + b0, acc[mt][nt][3] + b1);
            *(float2*)&C[(size_t)row * N + col]       = v0;
            *(float2*)&C[(size_t)(row + 8) * N + col] = v1;
        }
    }
}

// ---------------------------------------------------------------------------
// lstm_rec_pf: per-producer flags + per-slice overlap.
//   16 k-slices == 16 producer CTAs. Slice = half-warp (16 threads).
//   Each half-warp: wait own flag -> LDG 512B/256B chunk -> STS -> syncwarp
//   -> FFMA2 partials. Then CTA-wide: bar, reduce, gates, publish chunk +
//   per-producer flag (red.release after bar). hx double-buffered by t&1.
// Template: H, KP (k-pairs per slice), CB (col blocks), RS (row split)
//   H=256: KP=8, CB=16, RS=1   (slice=16 thr, chunk=128 floats)
//   H=128: KP=4, CB=8,  RS=2   (slice=16 thr, chunk=64 floats)
// ---------------------------------------------------------------------------
template <int H, int KP, int CB, int RS>
__global__ __launch_bounds__(256, 1) void lstm_rec_pf(
    const float* __restrict__ zx, const float* __restrict__ U,
    float* __restrict__ out, int* __restrict__ flags, float* __restrict__ hx)
{
    constexpr int N4   = 4 * H;
    constexpr int Bg   = 8;
    constexpr int SL   = 16;          // slices == producers
    constexpr int NH   = H / 16;      // cols per producer (16 / 8)
    constexpr int NCZ  = 4 * NH;
    constexpr int CW   = 4;
    constexpr int RT   = Bg / RS;
    constexpr int NRED = Bg * NH;
    constexpr int CHK  = Bg * NH;     // chunk floats (128 / 64)
    constexpr int TPS  = 256 / SL;    // 16 threads per slice
    constexpr int LDV  = CHK / TPS;   // floats loaded per thread (8 / 4)
    static_assert(SL * KP * 2 == H && CB * CW == NCZ && SL * CB * RS == 256, "split");
    static_assert(NH == 2 * KP, "chunk == slice k-range");

    __shared__ float hs[SL * CHK];         // staged chunks
    __shared__ float zp[SL * Bg * NCZ];    // split-K partials

    int tid = threadIdx.x;
    int g   = blockIdx.x >> 4;
    int cb  = blockIdx.x & 15;
    int jb  = cb * NH;

    // slice identity
    int s  = tid / TPS;                    // slice = producer index
    int u  = tid % TPS;
    int lane = tid & 31;
    unsigned halfmask = (lane < 16) ? 0x0000FFFFu : 0xFFFF0000u;

    // matmul identity within slice: u -> (cb2, rs)
    int cb2 = u / RS;
    int rs  = u % RS;

    // U slice -> registers (one-time). k-pair k2 = s*KP + kk (global).
    ull Ureg[KP][CW];
#pragma unroll
    for (int kk = 0; kk < KP; kk++)
#pragma unroll
        for (int cw = 0; cw < CW; cw++) {
            int c    = cb2 * CW + cw;
            int gi   = c / NH;
            int j    = c % NH;
            int gcol = gi * H + jb + j;
            int k2   = s * KP + kk;
            Ureg[kk][cw] = pack2(__ldg(&U[(size_t)(2 * k2) * N4 + gcol]),
                                 __ldg(&U[(size_t)(2 * k2 + 1) * N4 + gcol]));
        }

    // gate identity (tid < NRED)
    int rr = tid / NH;
    int jj = tid % NH;
    int bglob = g * Bg + rr;
    float creg = 0.f;

    int*   flagG = flags + g * (T_STEPS * 16);
    float* hxG   = hx + g * (2 * 16 * 128);    // stride uses max CHK=128
    const ull* hs2 = (const ull*)hs;

    __syncthreads();

    for (int t = 0; t < T_STEPS; t++) {
        // Prefetch zx (independent of h availability).
        float zx0 = 0.f, zx1 = 0.f, zx2 = 0.f, zx3 = 0.f;
        if (tid < NRED) {
            size_t basei = ((size_t)bglob * T_STEPS + t) * N4 + jb + jj;
            zx0 = zx[basei + 0 * (size_t)H];
            zx1 = zx[basei + 1 * (size_t)H];
            zx2 = zx[basei + 2 * (size_t)H];
            zx3 = zx[basei + 3 * (size_t)H];
        }

        float z0 = 0.f, z1 = 0.f, z2 = 0.f, z3 = 0.f;
        if (t > 0) {
            // Wait ONLY for our slice's producer, then stage its chunk.
            const int* fp = &flagG[(t - 1) * 16 + s];
            while (ld_acquire_gpu(fp) == 0) { }
            const float* src = &hxG[(((t - 1) & 1) * 16 + s) * 128];
#pragma unroll
            for (int q = 0; q < LDV; q += 4) {
                float4 v = *(const float4*)&src[u * LDV + q];
                *(float4*)&hs[s * CHK + u * LDV + q] = v;
            }
            __syncwarp(halfmask);

            // Slice matmul: rows rs*RT..  cols (cb2*CW..), k-pairs of slice s.
            ull acc[RT][CW];
#pragma unroll
            for (int i = 0; i < RT; i++)
#pragma unroll
                for (int cw = 0; cw < CW; cw++) acc[i][cw] = 0ull;

#pragma unroll
            for (int kk = 0; kk < KP; kk++) {
                ull hv[RT];
#pragma unroll
                for (int i = 0; i < RT; i++)
                    hv[i] = hs2[(s * Bg + rs * RT + i) * KP + kk];
#pragma unroll
                for (int i = 0; i < RT; i++)
#pragma unroll
                    for (int cw = 0; cw < CW; cw++)
                        acc[i][cw] = ffma2(hv[i], Ureg[kk][cw], acc[i][cw]);
            }
#pragma unroll
            for (int i = 0; i < RT; i++) {
                float4 v;
                v.x = sum2(acc[i][0]);
                v.y = sum2(acc[i][1]);
                v.z = sum2(acc[i][2]);
                v.w = sum2(acc[i][3]);
                *(float4*)&zp[(s * Bg + rs * RT + i) * NCZ + cb2 * CW] = v;
            }
            __syncthreads();                               // B1: zp ready

            if (tid < NRED) {
#pragma unroll
                for (int s2 = 0; s2 < SL; s2++) {
                    const float* zr = &zp[(s2 * Bg + rr) * NCZ];
                    z0 += zr[0 * NH + jj];
                    z1 += zr[1 * NH + jj];
                    z2 += zr[2 * NH + jj];
                    z3 += zr[3 * NH + jj];
                }
            }
        }

        // Gates + state; publish h chunk (out + hx) then flag.
        if (tid < NRED) {
            float zi = zx0 + z0, zf = zx1 + z1, zg = zx2 + z2, zo = zx3 + z3;
            float si = 1.f / (1.f + __expf(-zi));
            float sf = 1.f / (1.f + __expf(-zf));
            float so = 1.f / (1.f + __expf(-zo));
            float gg = zg > 0.f ? zg : 0.f;
            creg = sf * creg + si * gg;
            float cr = creg > 0.f ? creg : 0.f;
            float hval = so * cr;
            out[((size_t)bglob * T_STEPS + t) * H + jb + jj] = hval;
            hxG[((t & 1) * 16 + cb) * 128 + rr * NH + jj] = hval;
        }
        __syncthreads();                                   // B2: stores done, zp free
        if (tid == 0) red_release_gpu_add(&flagG[t * 16 + cb], 1);
    }
}

// ---------------------------------------------------------------------------
extern "C" void kernel_launch(void* const* d_in, const int* in_sizes, int n_in,
                              void* d_out, int out_size)
{
    const float* x  = (const float*)d_in[0];
    const float* W1 = (const float*)d_in[1];
    const float* U1 = (const float*)d_in[2];
    const float* b1 = (const float*)d_in[3];
    const float* W2 = (const float*)d_in[4];
    const float* U2 = (const float*)d_in[5];
    const float* b2 = (const float*)d_in[6];
    const float* W3 = (const float*)d_in[7];
    const float* U3 = (const float*)d_in[8];
    const float* b3 = (const float*)d_in[9];
    const float* W4 = (const float*)d_in[10];
    const float* U4 = (const float*)d_in[11];
    const float* b4 = (const float*)d_in[12];
    float* out = (float*)d_out;

    void *p;
    cudaGetSymbolAddress(&p, g_zx);    float* zx    = (float*)p;
    cudaGetSymbolAddress(&p, g_bufA);  float* bufA  = (float*)p;
    cudaGetSymbolAddress(&p, g_bufB);  float* bufB  = (float*)p;
    cudaGetSymbolAddress(&p, g_flags); int*   flags = (int*)p;
    cudaGetSymbolAddress(&p, g_hx);    float* hx    = (float*)p;
    cudaGetSymbolAddress(&p, g_ahi);   __nv_bfloat16* ahi  = (__nv_bfloat16*)p;
    cudaGetSymbolAddress(&p, g_alo);   __nv_bfloat16* alo  = (__nv_bfloat16*)p;
    cudaGetSymbolAddress(&p, g_wthi);  __nv_bfloat16* wthi = (__nv_bfloat16*)p;
    cudaGetSymbolAddress(&p, g_wtlo);  __nv_bfloat16* wtlo = (__nv_bfloat16*)p;

    const int M = BATCH * T_STEPS;  // 65536
    const int FLAYER = 8 * T_STEPS * 16;

    // Zero all 4 layers' per-producer flags (part of the graph; re-runs on replay).
    cudaMemsetAsync(flags, 0, 4 * (size_t)FLAYER * sizeof(int));

    // ---- Layer 1: F=256 -> H=256 ----
    split_bf16<<<M * 256 / 4 / 256, 256>>>(x, ahi, alo, M * 256 / 4);
    wsplit_t<<<dim3(1024 / 32, 256 / 32), dim3(32, 8)>>>(W1, wthi, wtlo, 256, 1024);
    gemm_mma_split<<<dim3(8, M / 128), 256>>>(ahi, alo, wthi, wtlo, b1, zx, M, 1024, 256);
    lstm_rec_pf<256, 8, 16, 1><<<128, 256>>>(zx, U1, bufA, flags + 0 * FLAYER, hx);

    // ---- Layer 2: F=256 -> H=128 ----
    split_bf16<<<M * 256 / 4 / 256, 256>>>(bufA, ahi, alo, M * 256 / 4);
    wsplit_t<<<dim3(512 / 32, 256 / 32), dim3(32, 8)>>>(W2, wthi, wtlo, 256, 512);
    gemm_mma_split<<<dim3(4, M / 128), 256>>>(ahi, alo, wthi, wtlo, b2, zx, M, 512, 256);
    lstm_rec_pf<128, 4, 8, 2><<<128, 256>>>(zx, U2, bufB, flags + 1 * FLAYER, hx);

    // ---- Layer 3: F=128 -> H=256 ----
    split_bf16<<<M * 128 / 4 / 256, 256>>>(bufB, ahi, alo, M * 128 / 4);
    wsplit_t<<<dim3(1024 / 32, 128 / 32), dim3(32, 8)>>>(W3, wthi, wtlo, 128, 1024);
    gemm_mma_split<<<dim3(8, M / 128), 256>>>(ahi, alo, wthi, wtlo, b3, zx, M, 1024, 128);
    lstm_rec_pf<256, 8, 16, 1><<<128, 256>>>(zx, U3, bufA, flags + 2 * FLAYER, hx);

    // ---- Layer 4: F=256 -> H=256 ----
    split_bf16<<<M * 256 / 4 / 256, 256>>>(bufA, ahi, alo, M * 256 / 4);
    wsplit_t<<<dim3(1024 / 32, 256 / 32), dim3(32, 8)>>>(W4, wthi, wtlo, 256, 1024);
    gemm_mma_split<<<dim3(8, M / 128), 256>>>(ahi, alo, wthi, wtlo, b4, zx, M, 1024, 256);
    lstm_rec_pf<256, 8, 16, 1><<<128, 256>>>(zx, U4, out, flags + 3 * FLAYER, hx);
}